// round 2
// baseline (speedup 1.0000x reference)
#include <cuda_runtime.h>
#include <cuda_bf16.h>
#include <math.h>

// ---------------------------------------------------------------------------
// CompactHash (Instant-NGP-style hash encoding with softmax codebook probing)
//
// BATCH=524288, INPUT_DIM=3, NUM_LEVELS=8, LEVEL_DIM=2, PROBE=16,
// INDEX_PARAMS=2^14, params per level = 2^min(12+3L,19)  (all powers of two!)
//
// Strategy:
//   Kernel 1: precompute softmax over every codebook row (131072 x 16)
//             -> kills 537M exp() calls from the hot loop.
//   Kernel 2: one warp per point. lane = (corner_sub(1b) , probe(4b)).
//             Each pass handles 2 corners: probe lane p reads normalized
//             weight (coalesced 64B/half-warp) and embedding float2
//             (coalesced 128B/half-warp, rows are contiguous because
//             h1*16 % params preserves 16-row alignment). Trilinear weight
//             folded per-lane; one 32-lane butterfly reduction per level.
// ---------------------------------------------------------------------------

#define NUM_LEVELS   8
#define PROBE        16
#define INDEX_PARAMS 16384
#define TOTAL_CB_ROWS (NUM_LEVELS * INDEX_PARAMS)   // 131072
#define BATCH        524288

// 8 MB scratch for normalized codebook (device global: no allocation APIs).
__device__ float g_cbnorm[TOTAL_CB_ROWS * PROBE];

// Row offsets of each level inside `embeddings`.
__constant__ int c_level_off[NUM_LEVELS] =
    {0, 4096, 36864, 299008, 823296, 1347584, 1871872, 2396160};

// -------------------------------- softmax prologue -------------------------
__global__ void __launch_bounds__(256)
softmax_cb_kernel(const float* __restrict__ cb)
{
    int row = blockIdx.x * blockDim.x + threadIdx.x;   // 0 .. 131071
    const float4* src = reinterpret_cast<const float4*>(cb + (size_t)row * PROBE);
    float4 v0 = __ldg(src + 0);
    float4 v1 = __ldg(src + 1);
    float4 v2 = __ldg(src + 2);
    float4 v3 = __ldg(src + 3);

    float e[16];
    // codebook values are tiny (|x| < 0.01): no max-subtraction needed.
    e[0]  = __expf(v0.x); e[1]  = __expf(v0.y); e[2]  = __expf(v0.z); e[3]  = __expf(v0.w);
    e[4]  = __expf(v1.x); e[5]  = __expf(v1.y); e[6]  = __expf(v1.z); e[7]  = __expf(v1.w);
    e[8]  = __expf(v2.x); e[9]  = __expf(v2.y); e[10] = __expf(v2.z); e[11] = __expf(v2.w);
    e[12] = __expf(v3.x); e[13] = __expf(v3.y); e[14] = __expf(v3.z); e[15] = __expf(v3.w);

    float s = 0.f;
#pragma unroll
    for (int i = 0; i < 16; i++) s += e[i];
    float inv = __fdividef(1.f, s);

    float4* dst = reinterpret_cast<float4*>(g_cbnorm + (size_t)row * PROBE);
    dst[0] = make_float4(e[0]*inv,  e[1]*inv,  e[2]*inv,  e[3]*inv);
    dst[1] = make_float4(e[4]*inv,  e[5]*inv,  e[6]*inv,  e[7]*inv);
    dst[2] = make_float4(e[8]*inv,  e[9]*inv,  e[10]*inv, e[11]*inv);
    dst[3] = make_float4(e[12]*inv, e[13]*inv, e[14]*inv, e[15]*inv);
}

// -------------------------------- main kernel ------------------------------
__global__ void __launch_bounds__(256)
compact_hash_kernel(const float*  __restrict__ inp,   // [BATCH,3]
                    const float2* __restrict__ emb,   // [TOTAL_EMB] rows of 2
                    float*        __restrict__ out)   // [BATCH,16]
{
    const int warp = (blockIdx.x * blockDim.x + threadIdx.x) >> 5;  // point id
    const int lane = threadIdx.x & 31;
    const int sub  = lane >> 4;      // which corner of the pair
    const int p    = lane & 15;      // probe index

    // point coordinates (warp-uniform broadcast loads)
    const float px = __ldg(inp + warp * 3 + 0);
    const float py = __ldg(inp + warp * 3 + 1);
    const float pz = __ldg(inp + warp * 3 + 2);

    float keep = 0.f;

#pragma unroll
    for (int L = 0; L < NUM_LEVELS; L++) {
        const float res = (float)(16 << L);
        const int   lp  = (12 + 3 * L < 19) ? (12 + 3 * L) : 19;
        const unsigned pm  = (1u << lp) - 1u;
        const int   off = c_level_off[L];

        const float fx = px * res, fy = py * res, fz = pz * res;
        const float ix = floorf(fx), iy = floorf(fy), iz = floorf(fz);
        const int   xi = (int)ix,    yi = (int)iy,    zi = (int)iz;
        const float xf = fx - ix,    yf = fy - iy,    zf = fz - iz;

        float acc0 = 0.f, acc1 = 0.f;

#pragma unroll
        for (int cp = 0; cp < 4; cp++) {
            const int c  = (cp << 1) | sub;      // corner 0..7
            const int bx = c & 1, by = (c >> 1) & 1, bz = (c >> 2) & 1;
            const unsigned cx = (unsigned)(xi + bx);
            const unsigned cy = (unsigned)(yi + by);
            const unsigned cz = (unsigned)(zi + bz);

            // fast spatial hashes (primes for dim0 are 1 -> plain xor)
            const unsigned h1 = cx ^ (cy * 2654435761u) ^ (cz * 805459861u);
            const unsigned h2 = cx ^ (cy * 2654435767u) ^ (cz * 805459871u);

            // ((h1 % params)*16 + p) % params == ((h1 & pm)*16 & pm) + p
            const unsigned base = ((h1 & pm) * 16u) & pm;
            const unsigned cbrow = (h2 & (INDEX_PARAMS - 1u)) + ((unsigned)L << 14);

            const float  w = __ldg(&g_cbnorm[(size_t)cbrow * PROBE + p]);
            const float2 e = __ldg(emb + off + base + p);

            const float wt = (bx ? xf : 1.f - xf) *
                             (by ? yf : 1.f - yf) *
                             (bz ? zf : 1.f - zf);
            const float ww = wt * w;
            acc0 = fmaf(ww, e.x, acc0);
            acc1 = fmaf(ww, e.y, acc1);
        }

        // reduce both components across all 32 lanes
#pragma unroll
        for (int s = 16; s; s >>= 1) {
            acc0 += __shfl_xor_sync(0xffffffffu, acc0, s);
            acc1 += __shfl_xor_sync(0xffffffffu, acc1, s);
        }
        // lane 2L keeps component 0, lane 2L+1 keeps component 1
        if ((lane >> 1) == L) keep = (lane & 1) ? acc1 : acc0;
    }

    // coalesced 64B store per warp
    if (lane < 16) out[(size_t)warp * 16 + lane] = keep;
}

// -------------------------------- launcher ---------------------------------
extern "C" void kernel_launch(void* const* d_in, const int* in_sizes, int n_in,
                              void* d_out, int out_size)
{
    const float*  inputs     = (const float*)d_in[0];   // [524288, 3]
    const float2* embeddings = (const float2*)d_in[1];  // [2920448, 2]
    const float*  code_book  = (const float*)d_in[2];   // [131072, 16]
    float*        out        = (float*)d_out;           // [524288, 16]

    // 1) normalize codebook rows (softmax)
    softmax_cb_kernel<<<TOTAL_CB_ROWS / 256, 256>>>(code_book);

    // 2) main gather: one warp per point (524288 warps, 8 warps/block)
    compact_hash_kernel<<<BATCH / 8, 256>>>(inputs, embeddings, out);
}

// round 3
// speedup vs baseline: 1.3054x; 1.3054x over previous
#include <cuda_runtime.h>
#include <cuda_bf16.h>
#include <math.h>

// ---------------------------------------------------------------------------
// CompactHash — R3: issue/ALU-bound fix.
//  - lane = (corner[2b], probe_pair[3b]); 4 corners per pass, 2 passes/level
//  - float4 embedding loads (2 probes/lane), float2 codebook loads
//  - hash via precomputed per-level products + single LOP3 xor per corner
//  - base = (h1<<4)&pm   (identity: ((h1%P)*16+p)%P, P=2^k, p<16)
// ---------------------------------------------------------------------------

#define NUM_LEVELS   8
#define PROBE        16
#define INDEX_PARAMS 16384
#define TOTAL_CB_ROWS (NUM_LEVELS * INDEX_PARAMS)   // 131072
#define BATCH        524288

// 8 MB scratch for normalized codebook (device global: no allocation APIs).
__device__ float g_cbnorm[TOTAL_CB_ROWS * PROBE];

__constant__ int c_level_off[NUM_LEVELS] =
    {0, 4096, 36864, 299008, 823296, 1347584, 1871872, 2396160};

// -------------------------------- softmax prologue -------------------------
__global__ void __launch_bounds__(256)
softmax_cb_kernel(const float* __restrict__ cb)
{
    int row = blockIdx.x * blockDim.x + threadIdx.x;   // 0 .. 131071
    const float4* src = reinterpret_cast<const float4*>(cb + (size_t)row * PROBE);
    float4 v0 = __ldg(src + 0);
    float4 v1 = __ldg(src + 1);
    float4 v2 = __ldg(src + 2);
    float4 v3 = __ldg(src + 3);

    float e[16];
    // codebook values are tiny (|x| < 0.01): no max-subtraction needed.
    e[0]  = __expf(v0.x); e[1]  = __expf(v0.y); e[2]  = __expf(v0.z); e[3]  = __expf(v0.w);
    e[4]  = __expf(v1.x); e[5]  = __expf(v1.y); e[6]  = __expf(v1.z); e[7]  = __expf(v1.w);
    e[8]  = __expf(v2.x); e[9]  = __expf(v2.y); e[10] = __expf(v2.z); e[11] = __expf(v2.w);
    e[12] = __expf(v3.x); e[13] = __expf(v3.y); e[14] = __expf(v3.z); e[15] = __expf(v3.w);

    float s = 0.f;
#pragma unroll
    for (int i = 0; i < 16; i++) s += e[i];
    float inv = __fdividef(1.f, s);

    float4* dst = reinterpret_cast<float4*>(g_cbnorm + (size_t)row * PROBE);
    dst[0] = make_float4(e[0]*inv,  e[1]*inv,  e[2]*inv,  e[3]*inv);
    dst[1] = make_float4(e[4]*inv,  e[5]*inv,  e[6]*inv,  e[7]*inv);
    dst[2] = make_float4(e[8]*inv,  e[9]*inv,  e[10]*inv, e[11]*inv);
    dst[3] = make_float4(e[12]*inv, e[13]*inv, e[14]*inv, e[15]*inv);
}

// -------------------------------- main kernel ------------------------------
__global__ void __launch_bounds__(256)
compact_hash_kernel(const float*  __restrict__ inp,   // [BATCH,3]
                    const float2* __restrict__ emb,   // [TOTAL_EMB] rows of 2
                    float*        __restrict__ out)   // [BATCH,16]
{
    const int warp = (blockIdx.x * blockDim.x + threadIdx.x) >> 5;  // point id
    const int lane = threadIdx.x & 31;
    const unsigned bx = (lane >> 3) & 1;   // corner x-bit (runtime, fixed/lane)
    const unsigned by = (lane >> 4) & 1;   // corner y-bit
    const int      pp = lane & 7;          // probe pair index (probes 2pp,2pp+1)

    const float px = __ldg(inp + warp * 3 + 0);
    const float py = __ldg(inp + warp * 3 + 1);
    const float pz = __ldg(inp + warp * 3 + 2);

    float keep = 0.f;

#pragma unroll
    for (int L = 0; L < NUM_LEVELS; L++) {
        const float    res = (float)(16 << L);
        const int      lp  = (12 + 3 * L < 19) ? (12 + 3 * L) : 19;
        const unsigned pm  = (1u << lp) - 1u;

        const float fx = px * res, fy = py * res, fz = pz * res;
        const float ix = floorf(fx), iy = floorf(fy), iz = floorf(fz);
        const float xf = fx - ix,    yf = fy - iy,    zf = fz - iz;
        const int   xi = (int)ix,    yi = (int)iy,    zi = (int)iz;

        // per-level hash precomputation (prime for dim 0 is 1)
        const unsigned xs  = (unsigned)xi + bx;
        const unsigned my  = (unsigned)yi * 2654435761u;
        const unsigned mz  = (unsigned)zi * 805459861u;
        const unsigned ny  = (unsigned)yi * 2654435767u;
        const unsigned nz  = (unsigned)zi * 805459871u;
        const unsigned hy1 = by ? (my + 2654435761u) : my;
        const unsigned hy2 = by ? (ny + 2654435767u) : ny;
        const unsigned mz1 = mz + 805459861u;
        const unsigned nz1 = nz + 805459871u;

        // per-lane trilinear xy factor; z factor picked per pass
        const float wxy = (bx ? xf : 1.f - xf) * (by ? yf : 1.f - yf);
        const float wz0 = 1.f - zf;

        const float4* __restrict__ embL =
            reinterpret_cast<const float4*>(emb + c_level_off[L]) + pp;
        const float2* __restrict__ cbL =
            reinterpret_cast<const float2*>(g_cbnorm) + ((size_t)L << 17) + pp;
            // (L*16384 rows) * 8 float2/row = L<<17

        float acc0 = 0.f, acc1 = 0.f;

#pragma unroll
        for (int pass = 0; pass < 2; pass++) {          // pass == bz
            const unsigned h1 = xs ^ hy1 ^ (pass ? mz1 : mz);
            const unsigned h2 = xs ^ hy2 ^ (pass ? nz1 : nz);

            const unsigned base = (h1 << 4) & pm;       // row base (mult of 16)
            const unsigned crow = h2 & (INDEX_PARAMS - 1u);

            const float4 e4 = __ldg(embL + (base >> 1));        // rows 2pp,2pp+1
            const float2 w2 = __ldg(cbL + crow * (PROBE / 2));  // weights 2pp,2pp+1

            const float wt  = wxy * (pass ? zf : wz0);
            const float ww0 = wt * w2.x;
            const float ww1 = wt * w2.y;
            acc0 = fmaf(ww0, e4.x, fmaf(ww1, e4.z, acc0));
            acc1 = fmaf(ww0, e4.y, fmaf(ww1, e4.w, acc1));
        }

        // reduce both components across all 32 lanes
#pragma unroll
        for (int s = 16; s; s >>= 1) {
            acc0 += __shfl_xor_sync(0xffffffffu, acc0, s);
            acc1 += __shfl_xor_sync(0xffffffffu, acc1, s);
        }
        if ((lane >> 1) == L) keep = (lane & 1) ? acc1 : acc0;
    }

    if (lane < 16) out[(size_t)warp * 16 + lane] = keep;
}

// -------------------------------- launcher ---------------------------------
extern "C" void kernel_launch(void* const* d_in, const int* in_sizes, int n_in,
                              void* d_out, int out_size)
{
    const float*  inputs     = (const float*)d_in[0];   // [524288, 3]
    const float2* embeddings = (const float2*)d_in[1];  // [2920448, 2]
    const float*  code_book  = (const float*)d_in[2];   // [131072, 16]
    float*        out        = (float*)d_out;           // [524288, 16]

    softmax_cb_kernel<<<TOTAL_CB_ROWS / 256, 256>>>(code_book);
    compact_hash_kernel<<<BATCH / 8, 256>>>(inputs, embeddings, out);
}

// round 4
// speedup vs baseline: 1.5265x; 1.1693x over previous
#include <cuda_runtime.h>
#include <cuda_bf16.h>
#include <math.h>

// ---------------------------------------------------------------------------
// CompactHash — R4: deferred multi-value reduction.
//  - lane = (corner_xy[2b], probe_pair[3b]); 4 corners/pass, 2 passes/level
//  - 16 fp32 accumulators per thread (one per output feature)
//  - single 5-stage multi-value butterfly epilogue (16 SHFL total vs 80)
//  - base = (h1<<4)&pm   (identity: ((h1%P)*16+p)%P, P=2^k, p<16)
// ---------------------------------------------------------------------------

#define NUM_LEVELS   8
#define PROBE        16
#define INDEX_PARAMS 16384
#define TOTAL_CB_ROWS (NUM_LEVELS * INDEX_PARAMS)   // 131072
#define BATCH        524288

// 8 MB scratch for normalized codebook (device global: no allocation APIs).
__device__ float g_cbnorm[TOTAL_CB_ROWS * PROBE];

__constant__ int c_level_off[NUM_LEVELS] =
    {0, 4096, 36864, 299008, 823296, 1347584, 1871872, 2396160};

// -------------------------------- softmax prologue -------------------------
__global__ void __launch_bounds__(256)
softmax_cb_kernel(const float* __restrict__ cb)
{
    int row = blockIdx.x * blockDim.x + threadIdx.x;   // 0 .. 131071
    const float4* src = reinterpret_cast<const float4*>(cb + (size_t)row * PROBE);
    float4 v0 = __ldg(src + 0);
    float4 v1 = __ldg(src + 1);
    float4 v2 = __ldg(src + 2);
    float4 v3 = __ldg(src + 3);

    float e[16];
    // codebook values are tiny (|x| < 0.01): no max-subtraction needed.
    e[0]  = __expf(v0.x); e[1]  = __expf(v0.y); e[2]  = __expf(v0.z); e[3]  = __expf(v0.w);
    e[4]  = __expf(v1.x); e[5]  = __expf(v1.y); e[6]  = __expf(v1.z); e[7]  = __expf(v1.w);
    e[8]  = __expf(v2.x); e[9]  = __expf(v2.y); e[10] = __expf(v2.z); e[11] = __expf(v2.w);
    e[12] = __expf(v3.x); e[13] = __expf(v3.y); e[14] = __expf(v3.z); e[15] = __expf(v3.w);

    float s = 0.f;
#pragma unroll
    for (int i = 0; i < 16; i++) s += e[i];
    float inv = __fdividef(1.f, s);

    float4* dst = reinterpret_cast<float4*>(g_cbnorm + (size_t)row * PROBE);
    dst[0] = make_float4(e[0]*inv,  e[1]*inv,  e[2]*inv,  e[3]*inv);
    dst[1] = make_float4(e[4]*inv,  e[5]*inv,  e[6]*inv,  e[7]*inv);
    dst[2] = make_float4(e[8]*inv,  e[9]*inv,  e[10]*inv, e[11]*inv);
    dst[3] = make_float4(e[12]*inv, e[13]*inv, e[14]*inv, e[15]*inv);
}

// -------------------------------- main kernel ------------------------------
__global__ void __launch_bounds__(256, 4)
compact_hash_kernel(const float*  __restrict__ inp,   // [BATCH,3]
                    const float2* __restrict__ emb,   // [TOTAL_EMB] rows of 2
                    float*        __restrict__ out)   // [BATCH,16]
{
    const int warp = (blockIdx.x * blockDim.x + threadIdx.x) >> 5;  // point id
    const int lane = threadIdx.x & 31;
    const unsigned bx = (lane >> 3) & 1;   // corner x-bit
    const unsigned by = (lane >> 4) & 1;   // corner y-bit
    const int      pp = lane & 7;          // probe pair index (probes 2pp,2pp+1)

    const float px = __ldg(inp + warp * 3 + 0);
    const float py = __ldg(inp + warp * 3 + 1);
    const float pz = __ldg(inp + warp * 3 + 2);

    float v[16];   // v[2L] = comp0 partial of level L, v[2L+1] = comp1
#pragma unroll
    for (int i = 0; i < 16; i++) v[i] = 0.f;

#pragma unroll
    for (int L = 0; L < NUM_LEVELS; L++) {
        const float    res = (float)(16 << L);
        const int      lp  = (12 + 3 * L < 19) ? (12 + 3 * L) : 19;
        const unsigned pm  = (1u << lp) - 1u;

        const float fx = px * res, fy = py * res, fz = pz * res;
        const float ix = floorf(fx), iy = floorf(fy), iz = floorf(fz);
        const float xf = fx - ix,    yf = fy - iy,    zf = fz - iz;
        const int   xi = (int)ix,    yi = (int)iy,    zi = (int)iz;

        // per-level hash precomputation (prime for dim 0 is 1)
        const unsigned xs  = (unsigned)xi + bx;
        const unsigned hy1 = ((unsigned)yi + by) * 2654435761u;
        const unsigned hy2 = ((unsigned)yi + by) * 2654435767u;
        const unsigned mz  = (unsigned)zi * 805459861u;
        const unsigned nz  = (unsigned)zi * 805459871u;
        const unsigned mz1 = mz + 805459861u;
        const unsigned nz1 = nz + 805459871u;

        // per-lane trilinear xy factor; z factor picked per (compile-time) pass
        const float wxy = (bx ? xf : 1.f - xf) * (by ? yf : 1.f - yf);
        const float wz0 = 1.f - zf;

        const float4* __restrict__ embL =
            reinterpret_cast<const float4*>(emb + c_level_off[L]) + pp;
        const float2* __restrict__ cbL =
            reinterpret_cast<const float2*>(g_cbnorm) + ((size_t)L << 17) + pp;

#pragma unroll
        for (int pass = 0; pass < 2; pass++) {          // pass == bz
            const unsigned h1 = xs ^ hy1 ^ (pass ? mz1 : mz);
            const unsigned h2 = xs ^ hy2 ^ (pass ? nz1 : nz);

            const unsigned base = (h1 << 4) & pm;       // row base (mult of 16)
            const unsigned crow = h2 & (INDEX_PARAMS - 1u);

            const float4 e4 = __ldg(embL + (base >> 1));        // rows 2pp,2pp+1
            const float2 w2 = __ldg(cbL + crow * (PROBE / 2));  // weights 2pp,2pp+1

            const float wt  = wxy * (pass ? zf : wz0);
            const float ww0 = wt * w2.x;
            const float ww1 = wt * w2.y;
            v[2*L]   = fmaf(ww0, e4.x, fmaf(ww1, e4.z, v[2*L]));
            v[2*L+1] = fmaf(ww0, e4.y, fmaf(ww1, e4.w, v[2*L+1]));
        }
    }

    // ---- multi-value butterfly reduction: 16 values over 32 lanes ----
    // Stages route value-bit b to lane-bit b (masks 1,2,4,8), then mask 16
    // final-reduces. Afterwards lane l holds feature (l & 15) summed over
    // all 32 lanes.
    float t8[8];
#pragma unroll
    for (int k = 0; k < 8; k++) {
        const float lo = v[2*k], hi = v[2*k+1];
        const float send = (lane & 1) ? lo : hi;
        const float recv = __shfl_xor_sync(0xffffffffu, send, 1);
        t8[k] = ((lane & 1) ? hi : lo) + recv;
    }
    float t4[4];
#pragma unroll
    for (int k = 0; k < 4; k++) {
        const float lo = t8[2*k], hi = t8[2*k+1];
        const float send = (lane & 2) ? lo : hi;
        const float recv = __shfl_xor_sync(0xffffffffu, send, 2);
        t4[k] = ((lane & 2) ? hi : lo) + recv;
    }
    float t2[2];
#pragma unroll
    for (int k = 0; k < 2; k++) {
        const float lo = t4[2*k], hi = t4[2*k+1];
        const float send = (lane & 4) ? lo : hi;
        const float recv = __shfl_xor_sync(0xffffffffu, send, 4);
        t2[k] = ((lane & 4) ? hi : lo) + recv;
    }
    float t1;
    {
        const float lo = t2[0], hi = t2[1];
        const float send = (lane & 8) ? lo : hi;
        const float recv = __shfl_xor_sync(0xffffffffu, send, 8);
        t1 = ((lane & 8) ? hi : lo) + recv;
    }
    const float r = t1 + __shfl_xor_sync(0xffffffffu, t1, 16);

    if (lane < 16) out[(size_t)warp * 16 + lane] = r;
}

// -------------------------------- launcher ---------------------------------
extern "C" void kernel_launch(void* const* d_in, const int* in_sizes, int n_in,
                              void* d_out, int out_size)
{
    const float*  inputs     = (const float*)d_in[0];   // [524288, 3]
    const float2* embeddings = (const float2*)d_in[1];  // [2920448, 2]
    const float*  code_book  = (const float*)d_in[2];   // [131072, 16]
    float*        out        = (float*)d_out;           // [524288, 16]

    softmax_cb_kernel<<<TOTAL_CB_ROWS / 256, 256>>>(code_book);
    compact_hash_kernel<<<BATCH / 8, 256>>>(inputs, embeddings, out);
}

// round 5
// speedup vs baseline: 1.5622x; 1.0234x over previous
#include <cuda_runtime.h>
#include <cuda_bf16.h>
#include <math.h>

// ---------------------------------------------------------------------------
// CompactHash — R5: one corner per lane, single pass per level.
//  - lane = (corner[3b], probe_quad[2b]); each lane: 4 probes of 1 corner
//  - per level: 1 float4 cb load + 2 float4 emb loads per lane, one pass
//  - hash: 1 LOP3 xor per lane from per-lane IMAD products
//  - 16 fp32 accumulators; 5-stage multi-value butterfly epilogue
// ---------------------------------------------------------------------------

#define NUM_LEVELS   8
#define PROBE        16
#define INDEX_PARAMS 16384
#define TOTAL_CB_ROWS (NUM_LEVELS * INDEX_PARAMS)   // 131072
#define BATCH        524288

// 8 MB scratch for normalized codebook (device global: no allocation APIs).
__device__ float g_cbnorm[TOTAL_CB_ROWS * PROBE];

__constant__ int c_level_off[NUM_LEVELS] =
    {0, 4096, 36864, 299008, 823296, 1347584, 1871872, 2396160};

// -------------------------------- softmax prologue -------------------------
__global__ void __launch_bounds__(256)
softmax_cb_kernel(const float* __restrict__ cb)
{
    int row = blockIdx.x * blockDim.x + threadIdx.x;   // 0 .. 131071
    const float4* src = reinterpret_cast<const float4*>(cb + (size_t)row * PROBE);
    float4 v0 = __ldg(src + 0);
    float4 v1 = __ldg(src + 1);
    float4 v2 = __ldg(src + 2);
    float4 v3 = __ldg(src + 3);

    float e[16];
    // codebook values are tiny (|x| < 0.01): no max-subtraction needed.
    e[0]  = __expf(v0.x); e[1]  = __expf(v0.y); e[2]  = __expf(v0.z); e[3]  = __expf(v0.w);
    e[4]  = __expf(v1.x); e[5]  = __expf(v1.y); e[6]  = __expf(v1.z); e[7]  = __expf(v1.w);
    e[8]  = __expf(v2.x); e[9]  = __expf(v2.y); e[10] = __expf(v2.z); e[11] = __expf(v2.w);
    e[12] = __expf(v3.x); e[13] = __expf(v3.y); e[14] = __expf(v3.z); e[15] = __expf(v3.w);

    float s = 0.f;
#pragma unroll
    for (int i = 0; i < 16; i++) s += e[i];
    float inv = __fdividef(1.f, s);

    float4* dst = reinterpret_cast<float4*>(g_cbnorm + (size_t)row * PROBE);
    dst[0] = make_float4(e[0]*inv,  e[1]*inv,  e[2]*inv,  e[3]*inv);
    dst[1] = make_float4(e[4]*inv,  e[5]*inv,  e[6]*inv,  e[7]*inv);
    dst[2] = make_float4(e[8]*inv,  e[9]*inv,  e[10]*inv, e[11]*inv);
    dst[3] = make_float4(e[12]*inv, e[13]*inv, e[14]*inv, e[15]*inv);
}

// -------------------------------- main kernel ------------------------------
__global__ void __launch_bounds__(256, 4)
compact_hash_kernel(const float*  __restrict__ inp,   // [BATCH,3]
                    const float2* __restrict__ emb,   // [TOTAL_EMB] rows of 2
                    float*        __restrict__ out)   // [BATCH,16]
{
    const int warp = (blockIdx.x * blockDim.x + threadIdx.x) >> 5;  // point id
    const int lane = threadIdx.x & 31;
    const unsigned bx = (lane >> 2) & 1;   // corner x-bit
    const unsigned by = (lane >> 3) & 1;   // corner y-bit
    const unsigned bz = (lane >> 4) & 1;   // corner z-bit
    const int      q  = lane & 3;          // probe quad (probes 4q..4q+3)

    const float px = __ldg(inp + warp * 3 + 0);
    const float py = __ldg(inp + warp * 3 + 1);
    const float pz = __ldg(inp + warp * 3 + 2);

    float v[16];   // v[2L] = comp0 partial of level L, v[2L+1] = comp1
#pragma unroll
    for (int i = 0; i < 16; i++) v[i] = 0.f;

#pragma unroll
    for (int L = 0; L < NUM_LEVELS; L++) {
        const float    res = (float)(16 << L);
        const int      lp  = (12 + 3 * L < 19) ? (12 + 3 * L) : 19;
        const unsigned pm  = (1u << lp) - 1u;

        const float fx = px * res, fy = py * res, fz = pz * res;
        const float ix = floorf(fx), iy = floorf(fy), iz = floorf(fz);
        const float xf = fx - ix,    yf = fy - iy,    zf = fz - iz;

        // per-lane corner coords + hashes (prime for dim 0 is 1)
        const unsigned xs = (unsigned)(int)ix + bx;
        const unsigned yb = (unsigned)(int)iy + by;
        const unsigned zb = (unsigned)(int)iz + bz;
        const unsigned h1 = xs ^ (yb * 2654435761u) ^ (zb * 805459861u);
        const unsigned h2 = xs ^ (yb * 2654435767u) ^ (zb * 805459871u);

        const unsigned base = (h1 << 4) & pm;           // emb row base (x16)
        const unsigned crow = h2 & (INDEX_PARAMS - 1u); // cb row within level

        // trilinear weight for this lane's corner
        const float wt = (bx ? xf : 1.f - xf) *
                         (by ? yf : 1.f - yf) *
                         (bz ? zf : 1.f - zf);

        const float4* __restrict__ embL =
            reinterpret_cast<const float4*>(emb + c_level_off[L]);
        const float4* __restrict__ cbL =
            reinterpret_cast<const float4*>(g_cbnorm) + ((size_t)L << 16);
            // (L*16384 rows) * 4 float4/row = L<<16

        // 4 probes: rows base+4q .. base+4q+3  (two float4 = 4 float2 rows)
        const float4 ea = __ldg(embL + (base >> 1) + 2 * q);
        const float4 eb = __ldg(embL + (base >> 1) + 2 * q + 1);
        const float4 w4 = __ldg(cbL + crow * 4 + q);

        // acc += wt * sum_i w_i * e_i   (reassociated: 1 MUL + 4 FMA / comp)
        float s0 = w4.x * ea.x;
        float s1 = w4.x * ea.y;
        s0 = fmaf(w4.y, ea.z, s0);
        s1 = fmaf(w4.y, ea.w, s1);
        s0 = fmaf(w4.z, eb.x, s0);
        s1 = fmaf(w4.z, eb.y, s1);
        s0 = fmaf(w4.w, eb.z, s0);
        s1 = fmaf(w4.w, eb.w, s1);
        v[2*L]   = fmaf(wt, s0, v[2*L]);
        v[2*L+1] = fmaf(wt, s1, v[2*L+1]);
    }

    // ---- multi-value butterfly reduction: 16 values over 32 lanes ----
    // Stages route value-bit b to lane-bit b (masks 1,2,4,8), then mask 16
    // final-reduces. Afterwards lane l holds feature (l & 15) summed over
    // all 32 lanes.
    float t8[8];
#pragma unroll
    for (int k = 0; k < 8; k++) {
        const float lo = v[2*k], hi = v[2*k+1];
        const float send = (lane & 1) ? lo : hi;
        const float recv = __shfl_xor_sync(0xffffffffu, send, 1);
        t8[k] = ((lane & 1) ? hi : lo) + recv;
    }
    float t4[4];
#pragma unroll
    for (int k = 0; k < 4; k++) {
        const float lo = t8[2*k], hi = t8[2*k+1];
        const float send = (lane & 2) ? lo : hi;
        const float recv = __shfl_xor_sync(0xffffffffu, send, 2);
        t4[k] = ((lane & 2) ? hi : lo) + recv;
    }
    float t2[2];
#pragma unroll
    for (int k = 0; k < 2; k++) {
        const float lo = t4[2*k], hi = t4[2*k+1];
        const float send = (lane & 4) ? lo : hi;
        const float recv = __shfl_xor_sync(0xffffffffu, send, 4);
        t2[k] = ((lane & 4) ? hi : lo) + recv;
    }
    float t1;
    {
        const float lo = t2[0], hi = t2[1];
        const float send = (lane & 8) ? lo : hi;
        const float recv = __shfl_xor_sync(0xffffffffu, send, 8);
        t1 = ((lane & 8) ? hi : lo) + recv;
    }
    const float r = t1 + __shfl_xor_sync(0xffffffffu, t1, 16);

    if (lane < 16) out[(size_t)warp * 16 + lane] = r;
}

// -------------------------------- launcher ---------------------------------
extern "C" void kernel_launch(void* const* d_in, const int* in_sizes, int n_in,
                              void* d_out, int out_size)
{
    const float*  inputs     = (const float*)d_in[0];   // [524288, 3]
    const float2* embeddings = (const float2*)d_in[1];  // [2920448, 2]
    const float*  code_book  = (const float*)d_in[2];   // [131072, 16]
    float*        out        = (float*)d_out;           // [524288, 16]

    softmax_cb_kernel<<<TOTAL_CB_ROWS / 256, 256>>>(code_book);
    compact_hash_kernel<<<BATCH / 8, 256>>>(inputs, embeddings, out);
}